// round 6
// baseline (speedup 1.0000x reference)
#include <cuda_runtime.h>
#include <cstdint>

// ---------------------------------------------------------------------------
// SelfAttention on GB300 (sm_103 base target).
// R5: all operands pre-split (hi/lo TF32) in global memory; GEMM is a clean
// cp.async double-buffered 128x128x32 mma.sync tf32 kernel (3 products = 3xTF32).
// K-projection writes K^T so the scores GEMM needs no in-loop transpose.
// ---------------------------------------------------------------------------

#define BATCH 4
#define DDIM  1024
#define NSEQ  2048
#define MH    1024
#define MV    1024

#define PROJ_SZ  ((size_t)BATCH * MH * NSEQ)     // 8M
#define SCORE_SZ ((size_t)BATCH * NSEQ * NSEQ)   // 16M

// ---- global scratch (allocation-free contract) ----
__device__ __align__(256) float g_xh[(size_t)BATCH * DDIM * NSEQ];
__device__ __align__(256) float g_xl[(size_t)BATCH * DDIM * NSEQ];
__device__ __align__(256) float g_wqh[(size_t)MH * DDIM];
__device__ __align__(256) float g_wql[(size_t)MH * DDIM];
__device__ __align__(256) float g_wkh[(size_t)MH * DDIM];
__device__ __align__(256) float g_wkl[(size_t)MH * DDIM];
__device__ __align__(256) float g_wvh[(size_t)MV * DDIM];
__device__ __align__(256) float g_wvl[(size_t)MV * DDIM];
__device__ __align__(256) float g_woh[(size_t)DDIM * MV];
__device__ __align__(256) float g_wol[(size_t)DDIM * MV];
__device__ __align__(256) float g_qh[PROJ_SZ];
__device__ __align__(256) float g_ql[PROJ_SZ];
__device__ __align__(256) float g_kth[PROJ_SZ];
__device__ __align__(256) float g_ktl[PROJ_SZ];
__device__ __align__(256) float g_vh[PROJ_SZ];
__device__ __align__(256) float g_vl[PROJ_SZ];
__device__ __align__(256) float g_s[SCORE_SZ];
__device__ __align__(256) float g_sh[SCORE_SZ];
__device__ __align__(256) float g_sl[SCORE_SZ];
__device__ __align__(256) float g_ah[PROJ_SZ];
__device__ __align__(256) float g_al[PROJ_SZ];

__device__ __forceinline__ void split2u(float x, uint32_t& h, uint32_t& l) {
    asm("cvt.rna.tf32.f32 %0, %1;" : "=r"(h) : "f"(x));
    float r = x - __uint_as_float(h);
    asm("cvt.rna.tf32.f32 %0, %1;" : "=r"(l) : "f"(r));
}
__device__ __forceinline__ void split2f(float x, float& h, float& l) {
    uint32_t hu, lu; split2u(x, hu, lu);
    h = __uint_as_float(hu); l = __uint_as_float(lu);
}

__device__ __forceinline__ void mma_tf32(float* c, const uint32_t* a, const uint32_t* b) {
    asm volatile(
        "mma.sync.aligned.m16n8k8.row.col.f32.tf32.tf32.f32 "
        "{%0,%1,%2,%3}, {%4,%5,%6,%7}, {%8,%9}, {%0,%1,%2,%3};"
        : "+f"(c[0]), "+f"(c[1]), "+f"(c[2]), "+f"(c[3])
        : "r"(a[0]), "r"(a[1]), "r"(a[2]), "r"(a[3]), "r"(b[0]), "r"(b[1]));
}

__device__ __forceinline__ uint32_t smem_u32(const void* p) {
    uint32_t a;
    asm("{ .reg .u64 t; cvta.to.shared.u64 t, %1; cvt.u32.u64 %0, t; }" : "=r"(a) : "l"(p));
    return a;
}
__device__ __forceinline__ void cpa16(uint32_t d, const void* s) {
    asm volatile("cp.async.cg.shared.global [%0], [%1], 16;" :: "r"(d), "l"(s));
}

// ---- smem stage layout (float offsets) ----
#define PA 36
#define PB 136
#define ST_AH 0
#define ST_AL 4608            // 128*36
#define ST_BH 9216
#define ST_BL 13568           // +32*136
#define ST_STRIDE 17920       // floats per stage (71680 B)
#define SMEM_BYTES (2 * ST_STRIDE * 4)   // 143360

// ---------------------------------------------------------------------------
// C[m,n] = sum_k A(m,k)B(k,n); A hi/lo k-contiguous [.. ,sA]; B hi/lo [sBk, ..].
// Tile 128x128x32, 256 thr, 8 warps (2m x 4n), warp tile 64x32.
// EPI: 0 = plain fp32 C;  1 = split (C=hi, C2=lo);  2 = split transposed.
// ---------------------------------------------------------------------------
template <int EPI>
__global__ void __launch_bounds__(256, 1)
gemm5(const float* __restrict__ Ah, const float* __restrict__ Al,
      const float* __restrict__ Bh, const float* __restrict__ Bl,
      float* __restrict__ C, float* __restrict__ C2,
      int K, long long sA, long long sBk, long long ldC,
      long long bA, long long bB, long long bC)
{
    extern __shared__ float sm[];
    const uint32_t smb = smem_u32(sm);

    const int tid = threadIdx.x, wid = tid >> 5, lane = tid & 31;
    const int gid = lane >> 2, tig = lane & 3;
    const int wm = (wid >> 2) << 6;    // 0, 64
    const int wn = (wid & 3) << 5;     // 0,32,64,96

    const float* Abh = Ah + (long long)blockIdx.z * bA;
    const float* Abl = Al + (long long)blockIdx.z * bA;
    const float* Bbh = Bh + (long long)blockIdx.z * bB;
    const float* Bbl = Bl + (long long)blockIdx.z * bB;
    const long long bm = (long long)blockIdx.y << 7;
    const long long bn = (long long)blockIdx.x << 7;

    float acc[4][4][4];
#pragma unroll
    for (int mt = 0; mt < 4; mt++)
#pragma unroll
        for (int nt = 0; nt < 4; nt++)
#pragma unroll
            for (int r = 0; r < 4; r++) acc[mt][nt][r] = 0.0f;

    // prefetch lambda (stage in {0,1}, k0)
    auto prefetch = [&](int stg, int k0) {
        const uint32_t s0 = smb + (uint32_t)(stg * ST_STRIDE * 4);
#pragma unroll
        for (int i = 0; i < 4; i++) {
            int idx = tid + (i << 8);                    // 0..1023
            int row = idx >> 3, c16 = (idx & 7) << 2;    // A: 128 rows x 8 chunks
            uint32_t d = s0 + (uint32_t)((row * PA + c16) << 2);
            cpa16(d,                      Abh + (long long)(bm + row) * sA + k0 + c16);
            cpa16(d + (ST_AL << 2),       Abl + (long long)(bm + row) * sA + k0 + c16);
        }
#pragma unroll
        for (int i = 0; i < 4; i++) {
            int idx = tid + (i << 8);
            int row = idx >> 5, c16 = (idx & 31) << 2;   // B: 32 rows x 32 chunks
            uint32_t d = s0 + (uint32_t)(((ST_BH + row * PB + c16)) << 2);
            cpa16(d,                      Bbh + (long long)(k0 + row) * sBk + bn + c16);
            cpa16(d + ((ST_BL - ST_BH) << 2), Bbl + (long long)(k0 + row) * sBk + bn + c16);
        }
    };

    const int nch = K >> 5;
    prefetch(0, 0);
    asm volatile("cp.async.commit_group;" ::: "memory");

    for (int ic = 0; ic < nch; ic++) {
        const int st = ic & 1;
        if (ic + 1 < nch) {
            prefetch(st ^ 1, (ic + 1) << 5);
            asm volatile("cp.async.commit_group;" ::: "memory");
            asm volatile("cp.async.wait_group 1;" ::: "memory");
        } else {
            asm volatile("cp.async.wait_group 0;" ::: "memory");
        }
        __syncthreads();

        const float* As_h = sm + st * ST_STRIDE + ST_AH;
        const float* As_l = sm + st * ST_STRIDE + ST_AL;
        const float* Bs_h = sm + st * ST_STRIDE + ST_BH;
        const float* Bs_l = sm + st * ST_STRIDE + ST_BL;

#pragma unroll
        for (int ks = 0; ks < 4; ks++) {
            const int kb = ks << 3;
            uint32_t ah[4][4], al[4][4], bh[4][2], bl[4][2];
#pragma unroll
            for (int mt = 0; mt < 4; mt++) {
                int r0 = wm + (mt << 4) + gid;
                int c0 = kb + tig;
                ah[mt][0] = __float_as_uint(As_h[r0 * PA + c0]);
                ah[mt][1] = __float_as_uint(As_h[(r0 + 8) * PA + c0]);
                ah[mt][2] = __float_as_uint(As_h[r0 * PA + c0 + 4]);
                ah[mt][3] = __float_as_uint(As_h[(r0 + 8) * PA + c0 + 4]);
                al[mt][0] = __float_as_uint(As_l[r0 * PA + c0]);
                al[mt][1] = __float_as_uint(As_l[(r0 + 8) * PA + c0]);
                al[mt][2] = __float_as_uint(As_l[r0 * PA + c0 + 4]);
                al[mt][3] = __float_as_uint(As_l[(r0 + 8) * PA + c0 + 4]);
            }
#pragma unroll
            for (int nt = 0; nt < 4; nt++) {
                int cc = wn + (nt << 3) + gid;
                bh[nt][0] = __float_as_uint(Bs_h[(kb + tig) * PB + cc]);
                bh[nt][1] = __float_as_uint(Bs_h[(kb + tig + 4) * PB + cc]);
                bl[nt][0] = __float_as_uint(Bs_l[(kb + tig) * PB + cc]);
                bl[nt][1] = __float_as_uint(Bs_l[(kb + tig + 4) * PB + cc]);
            }
#pragma unroll
            for (int mt = 0; mt < 4; mt++)
#pragma unroll
                for (int nt = 0; nt < 4; nt++) mma_tf32(acc[mt][nt], ah[mt], bh[nt]);
#pragma unroll
            for (int mt = 0; mt < 4; mt++)
#pragma unroll
                for (int nt = 0; nt < 4; nt++) mma_tf32(acc[mt][nt], ah[mt], bl[nt]);
#pragma unroll
            for (int mt = 0; mt < 4; mt++)
#pragma unroll
                for (int nt = 0; nt < 4; nt++) mma_tf32(acc[mt][nt], al[mt], bh[nt]);
        }
        __syncthreads();
    }

    // ---------------- epilogues ----------------
    if (EPI == 0 || EPI == 1) {
        float* Cb  = C  + (long long)blockIdx.z * bC;
        float* Cb2 = (EPI == 1) ? C2 + (long long)blockIdx.z * bC : nullptr;
#pragma unroll
        for (int mt = 0; mt < 4; mt++) {
            long long r0 = bm + wm + (mt << 4) + gid;
#pragma unroll
            for (int nt = 0; nt < 4; nt++) {
                long long cc = bn + wn + (nt << 3) + (tig << 1);
                if (EPI == 0) {
                    *reinterpret_cast<float2*>(Cb + r0 * ldC + cc)       = make_float2(acc[mt][nt][0], acc[mt][nt][1]);
                    *reinterpret_cast<float2*>(Cb + (r0 + 8) * ldC + cc) = make_float2(acc[mt][nt][2], acc[mt][nt][3]);
                } else {
                    float h0,l0,h1,l1,h2,l2,h3,l3;
                    split2f(acc[mt][nt][0], h0, l0); split2f(acc[mt][nt][1], h1, l1);
                    split2f(acc[mt][nt][2], h2, l2); split2f(acc[mt][nt][3], h3, l3);
                    *reinterpret_cast<float2*>(Cb  + r0 * ldC + cc)       = make_float2(h0, h1);
                    *reinterpret_cast<float2*>(Cb  + (r0 + 8) * ldC + cc) = make_float2(h2, h3);
                    *reinterpret_cast<float2*>(Cb2 + r0 * ldC + cc)       = make_float2(l0, l1);
                    *reinterpret_cast<float2*>(Cb2 + (r0 + 8) * ldC + cc) = make_float2(l2, l3);
                }
            }
        }
    } else {
        // EPI == 2: transposed split store (for K^T). Stage through smem.
        __syncthreads();
        float* esm = sm;                 // [128 m][pitch 129] floats
        const int PE = 129;
#pragma unroll
        for (int mt = 0; mt < 4; mt++) {
            int r = wm + (mt << 4) + gid;
#pragma unroll
            for (int nt = 0; nt < 4; nt++) {
                int c = wn + (nt << 3) + (tig << 1);
                esm[r * PE + c]           = acc[mt][nt][0];
                esm[r * PE + c + 1]       = acc[mt][nt][1];
                esm[(r + 8) * PE + c]     = acc[mt][nt][2];
                esm[(r + 8) * PE + c + 1] = acc[mt][nt][3];
            }
        }
        __syncthreads();
        float* Cb  = C  + (long long)blockIdx.z * bC;
        float* Cb2 = C2 + (long long)blockIdx.z * bC;
        const int n = tid & 127, ms = (tid >> 7) << 6;
        float* crh = Cb  + (bn + n) * ldC + bm + ms;
        float* crl = Cb2 + (bn + n) * ldC + bm + ms;
#pragma unroll
        for (int j = 0; j < 64; j += 4) {
            float h0,l0,h1,l1,h2,l2,h3,l3;
            split2f(esm[(ms + j + 0) * PE + n], h0, l0);
            split2f(esm[(ms + j + 1) * PE + n], h1, l1);
            split2f(esm[(ms + j + 2) * PE + n], h2, l2);
            split2f(esm[(ms + j + 3) * PE + n], h3, l3);
            *reinterpret_cast<float4*>(crh + j) = make_float4(h0, h1, h2, h3);
            *reinterpret_cast<float4*>(crl + j) = make_float4(l0, l1, l2, l3);
        }
    }
}

// ---------------- operand split (standalone, for raw inputs) ----------------
__global__ void __launch_bounds__(256)
split_arr(const float4* __restrict__ src, float4* __restrict__ h4,
          float4* __restrict__ l4, long long n4)
{
    for (long long i = blockIdx.x * 256ll + threadIdx.x; i < n4; i += (long long)gridDim.x * 256) {
        float4 v = src[i];
        float4 h, l;
        split2f(v.x, h.x, l.x); split2f(v.y, h.y, l.y);
        split2f(v.z, h.z, l.z); split2f(v.w, h.w, l.w);
        h4[i] = h; l4[i] = l;
    }
}

// ---------------- softmax over last dim, split output ----------------
__global__ void __launch_bounds__(256)
softmax_split(float* __restrict__ S, float* __restrict__ Sh, float* __restrict__ Sl, int N)
{
    float* row = S + (long long)blockIdx.x * N;
    float* rh  = Sh + (long long)blockIdx.x * N;
    float* rl  = Sl + (long long)blockIdx.x * N;
    const int tid = threadIdx.x;
    __shared__ float red[256];

    float m = -3.4e38f;
    for (int j = tid; j < N; j += 256) m = fmaxf(m, row[j]);
    red[tid] = m;
    __syncthreads();
    for (int s = 128; s > 0; s >>= 1) {
        if (tid < s) red[tid] = fmaxf(red[tid], red[tid + s]);
        __syncthreads();
    }
    m = red[0];
    __syncthreads();

    float sum = 0.0f;
    for (int j = tid; j < N; j += 256) {
        float e = __expf(row[j] - m);
        row[j] = e;
        sum += e;
    }
    red[tid] = sum;
    __syncthreads();
    for (int s = 128; s > 0; s >>= 1) {
        if (tid < s) red[tid] += red[tid + s];
        __syncthreads();
    }
    float inv = 1.0f / red[0];
    __syncthreads();
    for (int j = tid; j < N; j += 256) {
        float p = row[j] * inv;
        float h, l;
        split2f(p, h, l);
        rh[j] = h; rl[j] = l;
    }
}

extern "C" void kernel_launch(void* const* d_in, const int* in_sizes, int n_in,
                              void* d_out, int out_size)
{
    const float* x   = (const float*)d_in[0];
    const float* W_Q = (const float*)d_in[1];
    const float* W_K = (const float*)d_in[2];
    const float* W_V = (const float*)d_in[3];
    const float* W_O = (const float*)d_in[4];
    float*       out = (float*)d_out;

    float *xh,*xl,*wqh,*wql,*wkh,*wkl,*wvh,*wvl,*woh,*wol;
    float *qh,*ql,*kth,*ktl,*vh,*vl,*s,*sh,*sl,*ah,*al;
    cudaGetSymbolAddress((void**)&xh,  g_xh);  cudaGetSymbolAddress((void**)&xl,  g_xl);
    cudaGetSymbolAddress((void**)&wqh, g_wqh); cudaGetSymbolAddress((void**)&wql, g_wql);
    cudaGetSymbolAddress((void**)&wkh, g_wkh); cudaGetSymbolAddress((void**)&wkl, g_wkl);
    cudaGetSymbolAddress((void**)&wvh, g_wvh); cudaGetSymbolAddress((void**)&wvl, g_wvl);
    cudaGetSymbolAddress((void**)&woh, g_woh); cudaGetSymbolAddress((void**)&wol, g_wol);
    cudaGetSymbolAddress((void**)&qh,  g_qh);  cudaGetSymbolAddress((void**)&ql,  g_ql);
    cudaGetSymbolAddress((void**)&kth, g_kth); cudaGetSymbolAddress((void**)&ktl, g_ktl);
    cudaGetSymbolAddress((void**)&vh,  g_vh);  cudaGetSymbolAddress((void**)&vl,  g_vl);
    cudaGetSymbolAddress((void**)&s,   g_s);
    cudaGetSymbolAddress((void**)&sh,  g_sh);  cudaGetSymbolAddress((void**)&sl,  g_sl);
    cudaGetSymbolAddress((void**)&ah,  g_ah);  cudaGetSymbolAddress((void**)&al,  g_al);

    cudaFuncSetAttribute(gemm5<0>, cudaFuncAttributeMaxDynamicSharedMemorySize, SMEM_BYTES);
    cudaFuncSetAttribute(gemm5<1>, cudaFuncAttributeMaxDynamicSharedMemorySize, SMEM_BYTES);
    cudaFuncSetAttribute(gemm5<2>, cudaFuncAttributeMaxDynamicSharedMemorySize, SMEM_BYTES);

    const long long xB = (long long)DDIM * NSEQ;
    const long long pB = (long long)MH * NSEQ;
    const long long sB = (long long)NSEQ * NSEQ;

    // ---- split raw inputs ----
    split_arr<<<1024, 256>>>((const float4*)x,   (float4*)xh,  (float4*)xl,  (long long)BATCH * DDIM * NSEQ / 4);
    split_arr<<<256,  256>>>((const float4*)W_Q, (float4*)wqh, (float4*)wql, (long long)MH * DDIM / 4);
    split_arr<<<256,  256>>>((const float4*)W_K, (float4*)wkh, (float4*)wkl, (long long)MH * DDIM / 4);
    split_arr<<<256,  256>>>((const float4*)W_V, (float4*)wvh, (float4*)wvl, (long long)MV * DDIM / 4);
    split_arr<<<256,  256>>>((const float4*)W_O, (float4*)woh, (float4*)wol, (long long)DDIM * MV / 4);

    // Q = W_Q @ x  (split out)
    {
        dim3 g(NSEQ / 128, MH / 128, BATCH);
        gemm5<1><<<g, 256, SMEM_BYTES>>>(wqh, wql, xh, xl, qh, ql,
                                         DDIM, DDIM, NSEQ, NSEQ, 0, xB, pB);
        // K^T = (W_K @ x)^T  (split transposed out: kT[n][h], ldC = MH)
        gemm5<2><<<g, 256, SMEM_BYTES>>>(wkh, wkl, xh, xl, kth, ktl,
                                         DDIM, DDIM, NSEQ, MH, 0, xB, pB);
        gemm5<1><<<g, 256, SMEM_BYTES>>>(wvh, wvl, xh, xl, vh, vl,
                                         DDIM, DDIM, NSEQ, NSEQ, 0, xB, pB);
    }
    // scores[i,j] = sum_h kT[i,h] q[h,j]  (plain fp32 out)
    {
        dim3 g(NSEQ / 128, NSEQ / 128, BATCH);
        gemm5<0><<<g, 256, SMEM_BYTES>>>(kth, ktl, qh, ql, s, nullptr,
                                         MH, MH, NSEQ, NSEQ, pB, pB, sB);
    }
    softmax_split<<<BATCH * NSEQ, 256>>>(s, sh, sl, NSEQ);
    // attn = V @ S  (split out)
    {
        dim3 g(NSEQ / 128, MV / 128, BATCH);
        gemm5<1><<<g, 256, SMEM_BYTES>>>(vh, vl, sh, sl, ah, al,
                                         NSEQ, NSEQ, NSEQ, NSEQ, pB, sB, pB);
    }
    // out = W_O @ attn  (plain)
    {
        dim3 g(NSEQ / 128, DDIM / 128, BATCH);
        gemm5<0><<<g, 256, SMEM_BYTES>>>(woh, wol, ah, al, out, nullptr,
                                         MV, MV, NSEQ, NSEQ, 0, pB, xB);
    }
}

// round 8
// speedup vs baseline: 1.5093x; 1.5093x over previous
#include <cuda_runtime.h>
#include <cstdint>

// ---------------------------------------------------------------------------
// SelfAttention on GB300 (sm_103 base target).
// R6: R4's winning occupancy shape (128x64 tile, 2 CTAs/SM) + pre-split hi/lo
// operands in global (3xTF32), split fused into producer epilogues, K^T
// pre-transposed, cp.async tile loads. No in-loop cvt / transpose.
// ---------------------------------------------------------------------------

#define BATCH 4
#define DDIM  1024
#define NSEQ  2048
#define MH    1024
#define MV    1024

#define PROJ_SZ  ((size_t)BATCH * MH * NSEQ)
#define SCORE_SZ ((size_t)BATCH * NSEQ * NSEQ)

// ---- global scratch (allocation-free contract) ----
__device__ __align__(256) float g_xh[(size_t)BATCH * DDIM * NSEQ];
__device__ __align__(256) float g_xl[(size_t)BATCH * DDIM * NSEQ];
__device__ __align__(256) float g_wqh[(size_t)MH * DDIM];
__device__ __align__(256) float g_wql[(size_t)MH * DDIM];
__device__ __align__(256) float g_wkh[(size_t)MH * DDIM];
__device__ __align__(256) float g_wkl[(size_t)MH * DDIM];
__device__ __align__(256) float g_wvh[(size_t)MV * DDIM];
__device__ __align__(256) float g_wvl[(size_t)MV * DDIM];
__device__ __align__(256) float g_woh[(size_t)DDIM * MV];
__device__ __align__(256) float g_wol[(size_t)DDIM * MV];
__device__ __align__(256) float g_qh[PROJ_SZ];
__device__ __align__(256) float g_ql[PROJ_SZ];
__device__ __align__(256) float g_kth[PROJ_SZ];
__device__ __align__(256) float g_ktl[PROJ_SZ];
__device__ __align__(256) float g_vh[PROJ_SZ];
__device__ __align__(256) float g_vl[PROJ_SZ];
__device__ __align__(256) float g_s[SCORE_SZ];
__device__ __align__(256) float g_sh[SCORE_SZ];
__device__ __align__(256) float g_sl[SCORE_SZ];
__device__ __align__(256) float g_ah[PROJ_SZ];
__device__ __align__(256) float g_al[PROJ_SZ];

__device__ __forceinline__ void split2u(float x, uint32_t& h, uint32_t& l) {
    asm("cvt.rna.tf32.f32 %0, %1;" : "=r"(h) : "f"(x));
    float r = x - __uint_as_float(h);
    asm("cvt.rna.tf32.f32 %0, %1;" : "=r"(l) : "f"(r));
}
__device__ __forceinline__ void split2f(float x, float& h, float& l) {
    uint32_t hu, lu; split2u(x, hu, lu);
    h = __uint_as_float(hu); l = __uint_as_float(lu);
}

__device__ __forceinline__ void mma_tf32(float* c, const uint32_t* a, const uint32_t* b) {
    asm volatile(
        "mma.sync.aligned.m16n8k8.row.col.f32.tf32.tf32.f32 "
        "{%0,%1,%2,%3}, {%4,%5,%6,%7}, {%8,%9}, {%0,%1,%2,%3};"
        : "+f"(c[0]), "+f"(c[1]), "+f"(c[2]), "+f"(c[3])
        : "r"(a[0]), "r"(a[1]), "r"(a[2]), "r"(a[3]), "r"(b[0]), "r"(b[1]));
}

__device__ __forceinline__ uint32_t smem_u32(const void* p) {
    uint32_t a;
    asm("{ .reg .u64 t; cvta.to.shared.u64 t, %1; cvt.u32.u64 %0, t; }" : "=r"(a) : "l"(p));
    return a;
}
__device__ __forceinline__ void cpa16(uint32_t d, const void* s) {
    asm volatile("cp.async.cg.shared.global [%0], [%1], 16;" :: "r"(d), "l"(s));
}

// ---- smem layout (float offsets), single stage ----
#define PA 36
#define PB 72
#define SA_H 0
#define SA_L 4608              // 128*36
#define SB_H 9216
#define SB_L 11520             // +32*72
#define SMEM_FLOATS 13824      // 55296 B per CTA -> 2 CTAs/SM
#define SMEM_BYTES (SMEM_FLOATS * 4)

// ---------------------------------------------------------------------------
// C[m,n] = sum_k A(m,k)B(k,n); A hi/lo k-contiguous; B hi/lo n-contiguous.
// Tile 128(M) x 64(N) x 32(K). 256 thr, 8 warps (4m x 2n), warp tile 32x32.
// EPI: 0 = plain fp32; 1 = split hi/lo; 2 = split transposed (for K^T).
// ---------------------------------------------------------------------------
template <int EPI>
__global__ void __launch_bounds__(256, 2)
gemm6(const float* __restrict__ Ah, const float* __restrict__ Al,
      const float* __restrict__ Bh, const float* __restrict__ Bl,
      float* __restrict__ C, float* __restrict__ C2,
      int K, long long sA, long long sBk, long long ldC,
      long long bA, long long bB, long long bC)
{
    extern __shared__ float sm[];
    const uint32_t smb = smem_u32(sm);

    const int tid = threadIdx.x, wid = tid >> 5, lane = tid & 31;
    const int gid = lane >> 2, tig = lane & 3;
    const int wm = (wid & 3) << 5;     // 0,32,64,96
    const int wn = (wid >> 2) << 5;    // 0,32

    const float* Abh = Ah + (long long)blockIdx.z * bA;
    const float* Abl = Al + (long long)blockIdx.z * bA;
    const float* Bbh = Bh + (long long)blockIdx.z * bB;
    const float* Bbl = Bl + (long long)blockIdx.z * bB;
    const long long bm = (long long)blockIdx.y << 7;
    const long long bn = (long long)blockIdx.x << 6;

    float acc[2][4][4];
#pragma unroll
    for (int mt = 0; mt < 2; mt++)
#pragma unroll
        for (int nt = 0; nt < 4; nt++)
#pragma unroll
            for (int r = 0; r < 4; r++) acc[mt][nt][r] = 0.0f;

    for (int k0 = 0; k0 < K; k0 += 32) {
        // ---- cp.async tile loads: A 128x32 hi/lo, B 32x64 hi/lo ----
#pragma unroll
        for (int i = 0; i < 4; i++) {
            int idx = tid + (i << 8);                 // 0..1023
            int row = idx >> 3, c4 = (idx & 7) << 2;  // A: 8 f4/row
            uint32_t d = smb + (uint32_t)((row * PA + c4) << 2);
            cpa16(d,                 Abh + (long long)(bm + row) * sA + k0 + c4);
            cpa16(d + (SA_L << 2),   Abl + (long long)(bm + row) * sA + k0 + c4);
        }
#pragma unroll
        for (int i = 0; i < 2; i++) {
            int idx = tid + (i << 8);                 // 0..511
            int row = idx >> 4, c4 = (idx & 15) << 2; // B: 16 f4/row
            uint32_t d = smb + (uint32_t)(((SB_H + row * PB + c4)) << 2);
            cpa16(d,                         Bbh + (long long)(k0 + row) * sBk + bn + c4);
            cpa16(d + ((SB_L - SB_H) << 2),  Bbl + (long long)(k0 + row) * sBk + bn + c4);
        }
        asm volatile("cp.async.commit_group;" ::: "memory");
        asm volatile("cp.async.wait_group 0;" ::: "memory");
        __syncthreads();

        const float* As_h = sm + SA_H;
        const float* As_l = sm + SA_L;
        const float* Bs_h = sm + SB_H;
        const float* Bs_l = sm + SB_L;

#pragma unroll
        for (int ks = 0; ks < 4; ks++) {
            const int kb = ks << 3;
            uint32_t ah[2][4], al[2][4], bh[4][2], bl[4][2];
#pragma unroll
            for (int mt = 0; mt < 2; mt++) {
                int r0 = wm + (mt << 4) + gid;
                int c0 = kb + tig;
                ah[mt][0] = __float_as_uint(As_h[r0 * PA + c0]);
                ah[mt][1] = __float_as_uint(As_h[(r0 + 8) * PA + c0]);
                ah[mt][2] = __float_as_uint(As_h[r0 * PA + c0 + 4]);
                ah[mt][3] = __float_as_uint(As_h[(r0 + 8) * PA + c0 + 4]);
                al[mt][0] = __float_as_uint(As_l[r0 * PA + c0]);
                al[mt][1] = __float_as_uint(As_l[(r0 + 8) * PA + c0]);
                al[mt][2] = __float_as_uint(As_l[r0 * PA + c0 + 4]);
                al[mt][3] = __float_as_uint(As_l[(r0 + 8) * PA + c0 + 4]);
            }
#pragma unroll
            for (int nt = 0; nt < 4; nt++) {
                int cc = wn + (nt << 3) + gid;
                bh[nt][0] = __float_as_uint(Bs_h[(kb + tig) * PB + cc]);
                bh[nt][1] = __float_as_uint(Bs_h[(kb + tig + 4) * PB + cc]);
                bl[nt][0] = __float_as_uint(Bs_l[(kb + tig) * PB + cc]);
                bl[nt][1] = __float_as_uint(Bs_l[(kb + tig + 4) * PB + cc]);
            }
#pragma unroll
            for (int mt = 0; mt < 2; mt++)
#pragma unroll
                for (int nt = 0; nt < 4; nt++) mma_tf32(acc[mt][nt], ah[mt], bh[nt]);
#pragma unroll
            for (int mt = 0; mt < 2; mt++)
#pragma unroll
                for (int nt = 0; nt < 4; nt++) mma_tf32(acc[mt][nt], ah[mt], bl[nt]);
#pragma unroll
            for (int mt = 0; mt < 2; mt++)
#pragma unroll
                for (int nt = 0; nt < 4; nt++) mma_tf32(acc[mt][nt], al[mt], bh[nt]);
        }
        __syncthreads();
    }

    // ---------------- epilogues ----------------
    if (EPI == 0 || EPI == 1) {
        float* Cb  = C + (long long)blockIdx.z * bC;
        float* Cb2 = (EPI == 1) ? C2 + (long long)blockIdx.z * bC : nullptr;
#pragma unroll
        for (int mt = 0; mt < 2; mt++) {
            long long r0 = bm + wm + (mt << 4) + gid;
#pragma unroll
            for (int nt = 0; nt < 4; nt++) {
                long long cc = bn + wn + (nt << 3) + (tig << 1);
                if (EPI == 0) {
                    *reinterpret_cast<float2*>(Cb + r0 * ldC + cc)       = make_float2(acc[mt][nt][0], acc[mt][nt][1]);
                    *reinterpret_cast<float2*>(Cb + (r0 + 8) * ldC + cc) = make_float2(acc[mt][nt][2], acc[mt][nt][3]);
                } else {
                    float h0,l0,h1,l1,h2,l2,h3,l3;
                    split2f(acc[mt][nt][0], h0, l0); split2f(acc[mt][nt][1], h1, l1);
                    split2f(acc[mt][nt][2], h2, l2); split2f(acc[mt][nt][3], h3, l3);
                    *reinterpret_cast<float2*>(Cb  + r0 * ldC + cc)       = make_float2(h0, h1);
                    *reinterpret_cast<float2*>(Cb  + (r0 + 8) * ldC + cc) = make_float2(h2, h3);
                    *reinterpret_cast<float2*>(Cb2 + r0 * ldC + cc)       = make_float2(l0, l1);
                    *reinterpret_cast<float2*>(Cb2 + (r0 + 8) * ldC + cc) = make_float2(l2, l3);
                }
            }
        }
    } else {
        // EPI == 2: transposed split store (K^T). Stage C tile [128m x 64n] in smem.
        float* esm = sm;                 // pitch 65
        const int PE = 65;
#pragma unroll
        for (int mt = 0; mt < 2; mt++) {
            int r = wm + (mt << 4) + gid;
#pragma unroll
            for (int nt = 0; nt < 4; nt++) {
                int c = wn + (nt << 3) + (tig << 1);
                esm[r * PE + c]           = acc[mt][nt][0];
                esm[r * PE + c + 1]       = acc[mt][nt][1];
                esm[(r + 8) * PE + c]     = acc[mt][nt][2];
                esm[(r + 8) * PE + c + 1] = acc[mt][nt][3];
            }
        }
        __syncthreads();
        float* Cb  = C  + (long long)blockIdx.z * bC;
        float* Cb2 = C2 + (long long)blockIdx.z * bC;
        const int n = tid >> 2, ms = (tid & 3) << 5;     // n 0..63, m-seg 0..96
        float* crh = Cb  + (bn + n) * ldC + bm + ms;
        float* crl = Cb2 + (bn + n) * ldC + bm + ms;
#pragma unroll
        for (int j = 0; j < 32; j += 4) {
            float h0,l0,h1,l1,h2,l2,h3,l3;
            split2f(esm[(ms + j + 0) * PE + n], h0, l0);
            split2f(esm[(ms + j + 1) * PE + n], h1, l1);
            split2f(esm[(ms + j + 2) * PE + n], h2, l2);
            split2f(esm[(ms + j + 3) * PE + n], h3, l3);
            *reinterpret_cast<float4*>(crh + j) = make_float4(h0, h1, h2, h3);
            *reinterpret_cast<float4*>(crl + j) = make_float4(l0, l1, l2, l3);
        }
    }
}

// ---------------- operand split (raw inputs) ----------------
__global__ void __launch_bounds__(256)
split_arr(const float4* __restrict__ src, float4* __restrict__ h4,
          float4* __restrict__ l4, long long n4)
{
    for (long long i = blockIdx.x * 256ll + threadIdx.x; i < n4; i += (long long)gridDim.x * 256) {
        float4 v = src[i];
        float4 h, l;
        split2f(v.x, h.x, l.x); split2f(v.y, h.y, l.y);
        split2f(v.z, h.z, l.z); split2f(v.w, h.w, l.w);
        h4[i] = h; l4[i] = l;
    }
}

// ---------------- softmax over last dim, split output ----------------
__global__ void __launch_bounds__(256)
softmax_split(float* __restrict__ S, float* __restrict__ Sh, float* __restrict__ Sl, int N)
{
    float* row = S + (long long)blockIdx.x * N;
    float* rh  = Sh + (long long)blockIdx.x * N;
    float* rl  = Sl + (long long)blockIdx.x * N;
    const int tid = threadIdx.x;
    __shared__ float red[256];

    float m = -3.4e38f;
    for (int j = tid; j < N; j += 256) m = fmaxf(m, row[j]);
    red[tid] = m;
    __syncthreads();
    for (int s = 128; s > 0; s >>= 1) {
        if (tid < s) red[tid] = fmaxf(red[tid], red[tid + s]);
        __syncthreads();
    }
    m = red[0];
    __syncthreads();

    float sum = 0.0f;
    for (int j = tid; j < N; j += 256) {
        float e = __expf(row[j] - m);
        row[j] = e;
        sum += e;
    }
    red[tid] = sum;
    __syncthreads();
    for (int s = 128; s > 0; s >>= 1) {
        if (tid < s) red[tid] += red[tid + s];
        __syncthreads();
    }
    float inv = 1.0f / red[0];
    __syncthreads();
    for (int j = tid; j < N; j += 256) {
        float p = row[j] * inv;
        float h, l;
        split2f(p, h, l);
        rh[j] = h; rl[j] = l;
    }
}

extern "C" void kernel_launch(void* const* d_in, const int* in_sizes, int n_in,
                              void* d_out, int out_size)
{
    const float* x   = (const float*)d_in[0];
    const float* W_Q = (const float*)d_in[1];
    const float* W_K = (const float*)d_in[2];
    const float* W_V = (const float*)d_in[3];
    const float* W_O = (const float*)d_in[4];
    float*       out = (float*)d_out;

    float *xh,*xl,*wqh,*wql,*wkh,*wkl,*wvh,*wvl,*woh,*wol;
    float *qh,*ql,*kth,*ktl,*vh,*vl,*s,*sh,*sl,*ah,*al;
    cudaGetSymbolAddress((void**)&xh,  g_xh);  cudaGetSymbolAddress((void**)&xl,  g_xl);
    cudaGetSymbolAddress((void**)&wqh, g_wqh); cudaGetSymbolAddress((void**)&wql, g_wql);
    cudaGetSymbolAddress((void**)&wkh, g_wkh); cudaGetSymbolAddress((void**)&wkl, g_wkl);
    cudaGetSymbolAddress((void**)&wvh, g_wvh); cudaGetSymbolAddress((void**)&wvl, g_wvl);
    cudaGetSymbolAddress((void**)&woh, g_woh); cudaGetSymbolAddress((void**)&wol, g_wol);
    cudaGetSymbolAddress((void**)&qh,  g_qh);  cudaGetSymbolAddress((void**)&ql,  g_ql);
    cudaGetSymbolAddress((void**)&kth, g_kth); cudaGetSymbolAddress((void**)&ktl, g_ktl);
    cudaGetSymbolAddress((void**)&vh,  g_vh);  cudaGetSymbolAddress((void**)&vl,  g_vl);
    cudaGetSymbolAddress((void**)&s,   g_s);
    cudaGetSymbolAddress((void**)&sh,  g_sh);  cudaGetSymbolAddress((void**)&sl,  g_sl);
    cudaGetSymbolAddress((void**)&ah,  g_ah);  cudaGetSymbolAddress((void**)&al,  g_al);

    cudaFuncSetAttribute(gemm6<0>, cudaFuncAttributeMaxDynamicSharedMemorySize, SMEM_BYTES);
    cudaFuncSetAttribute(gemm6<1>, cudaFuncAttributeMaxDynamicSharedMemorySize, SMEM_BYTES);
    cudaFuncSetAttribute(gemm6<2>, cudaFuncAttributeMaxDynamicSharedMemorySize, SMEM_BYTES);

    const long long xB = (long long)DDIM * NSEQ;
    const long long pB = (long long)MH * NSEQ;
    const long long sB = (long long)NSEQ * NSEQ;

    // ---- split raw inputs ----
    split_arr<<<1024, 256>>>((const float4*)x,   (float4*)xh,  (float4*)xl,  (long long)BATCH * DDIM * NSEQ / 4);
    split_arr<<<256,  256>>>((const float4*)W_Q, (float4*)wqh, (float4*)wql, (long long)MH * DDIM / 4);
    split_arr<<<256,  256>>>((const float4*)W_K, (float4*)wkh, (float4*)wkl, (long long)MH * DDIM / 4);
    split_arr<<<256,  256>>>((const float4*)W_V, (float4*)wvh, (float4*)wvl, (long long)MV * DDIM / 4);
    split_arr<<<256,  256>>>((const float4*)W_O, (float4*)woh, (float4*)wol, (long long)DDIM * MV / 4);

    // QKV projections (split outputs; K transposed)
    {
        dim3 g(NSEQ / 64, MH / 128, BATCH);
        gemm6<1><<<g, 256, SMEM_BYTES>>>(wqh, wql, xh, xl, qh, ql,
                                         DDIM, DDIM, NSEQ, NSEQ, 0, xB, pB);
        gemm6<2><<<g, 256, SMEM_BYTES>>>(wkh, wkl, xh, xl, kth, ktl,
                                         DDIM, DDIM, NSEQ, MH, 0, xB, pB);
        gemm6<1><<<g, 256, SMEM_BYTES>>>(wvh, wvl, xh, xl, vh, vl,
                                         DDIM, DDIM, NSEQ, NSEQ, 0, xB, pB);
    }
    // scores[i,j] = sum_h kT[i,h] q[h,j]  (plain out)
    {
        dim3 g(NSEQ / 64, NSEQ / 128, BATCH);
        gemm6<0><<<g, 256, SMEM_BYTES>>>(kth, ktl, qh, ql, s, nullptr,
                                         MH, MH, NSEQ, NSEQ, pB, pB, sB);
    }
    softmax_split<<<BATCH * NSEQ, 256>>>(s, sh, sl, NSEQ);
    // attn = V @ S (split out)
    {
        dim3 g(NSEQ / 64, MV / 128, BATCH);
        gemm6<1><<<g, 256, SMEM_BYTES>>>(vh, vl, sh, sl, ah, al,
                                         NSEQ, NSEQ, NSEQ, NSEQ, pB, sB, pB);
    }
    // out = W_O @ attn (plain)
    {
        dim3 g(NSEQ / 64, DDIM / 128, BATCH);
        gemm6<0><<<g, 256, SMEM_BYTES>>>(woh, wol, ah, al, out, nullptr,
                                         MV, MV, NSEQ, NSEQ, 0, pB, xB);
    }
}

// round 9
// speedup vs baseline: 2.8929x; 1.9167x over previous
#include <cuda_runtime.h>
#include <cuda_fp16.h>
#include <cstdint>

// ---------------------------------------------------------------------------
// SelfAttention on GB300 (sm_103 base target).
// R7: 3-product FP16 split (h+l, 22-bit effective) on mma.m16n8k16.f16 —
// 2x MACs/instr and half the bytes of the tf32 scheme. All operands pre-split
// and f16x2-packed in global; packing fused into producer epilogues/softmax.
// CTA 128x64, warp 32x32, 2 CTAs/SM (R4's proven occupancy shape), Kchunk 64.
// ---------------------------------------------------------------------------

#define BATCH 4
#define DDIM  1024
#define NSEQ  2048
#define MH    1024
#define MV    1024

// ---- packed global scratch (uint32 = f16x2). Allocation-free contract. ----
__device__ __align__(256) uint32_t g_xBh[(size_t)BATCH * (DDIM/2) * NSEQ];
__device__ __align__(256) uint32_t g_xBl[(size_t)BATCH * (DDIM/2) * NSEQ];
__device__ __align__(256) uint32_t g_wqh[(size_t)MH * (DDIM/2)];
__device__ __align__(256) uint32_t g_wql[(size_t)MH * (DDIM/2)];
__device__ __align__(256) uint32_t g_wkh[(size_t)MH * (DDIM/2)];
__device__ __align__(256) uint32_t g_wkl[(size_t)MH * (DDIM/2)];
__device__ __align__(256) uint32_t g_wvh[(size_t)MV * (DDIM/2)];
__device__ __align__(256) uint32_t g_wvl[(size_t)MV * (DDIM/2)];
__device__ __align__(256) uint32_t g_woh[(size_t)DDIM * (MV/2)];
__device__ __align__(256) uint32_t g_wol[(size_t)DDIM * (MV/2)];
__device__ __align__(256) uint32_t g_qBh[(size_t)BATCH * (MH/2) * NSEQ];
__device__ __align__(256) uint32_t g_qBl[(size_t)BATCH * (MH/2) * NSEQ];
__device__ __align__(256) uint32_t g_ktAh[(size_t)BATCH * NSEQ * (MH/2)];
__device__ __align__(256) uint32_t g_ktAl[(size_t)BATCH * NSEQ * (MH/2)];
__device__ __align__(256) uint32_t g_vAh[(size_t)BATCH * MV * (NSEQ/2)];
__device__ __align__(256) uint32_t g_vAl[(size_t)BATCH * MV * (NSEQ/2)];
__device__ __align__(256) float    g_s[(size_t)BATCH * NSEQ * NSEQ];
__device__ __align__(256) uint32_t g_sBh[(size_t)BATCH * (NSEQ/2) * NSEQ];
__device__ __align__(256) uint32_t g_sBl[(size_t)BATCH * (NSEQ/2) * NSEQ];
__device__ __align__(256) uint32_t g_aBh[(size_t)BATCH * (MV/2) * NSEQ];
__device__ __align__(256) uint32_t g_aBl[(size_t)BATCH * (MV/2) * NSEQ];

// ---- helpers ----
__device__ __forceinline__ uint32_t pack2(float a, float b) {
    __half2 h = __halves2half2(__float2half_rn(a), __float2half_rn(b));
    return *reinterpret_cast<uint32_t*>(&h);
}
// split pair (x0,x1) -> packed hi word + packed lo word
__device__ __forceinline__ void splitpack(float x0, float x1, uint32_t& hw, uint32_t& lw) {
    float h0 = __half2float(__float2half_rn(x0));
    float h1 = __half2float(__float2half_rn(x1));
    hw = pack2(h0, h1);
    lw = pack2(x0 - h0, x1 - h1);
}

__device__ __forceinline__ void mma_f16(float* c, const uint32_t* a, const uint32_t* b) {
    asm volatile(
        "mma.sync.aligned.m16n8k16.row.col.f32.f16.f16.f32 "
        "{%0,%1,%2,%3}, {%4,%5,%6,%7}, {%8,%9}, {%0,%1,%2,%3};"
        : "+f"(c[0]), "+f"(c[1]), "+f"(c[2]), "+f"(c[3])
        : "r"(a[0]), "r"(a[1]), "r"(a[2]), "r"(a[3]), "r"(b[0]), "r"(b[1]));
}

__device__ __forceinline__ uint32_t smem_u32(const void* p) {
    uint32_t a;
    asm("{ .reg .u64 t; cvta.to.shared.u64 t, %1; cvt.u32.u64 %0, t; }" : "=r"(a) : "l"(p));
    return a;
}
__device__ __forceinline__ void cpa16(uint32_t d, const void* s) {
    asm volatile("cp.async.cg.shared.global [%0], [%1], 16;" :: "r"(d), "l"(s));
}

// ---- smem layout (word offsets), single stage, Kchunk = 64 elems = 32 words ----
#define PAW 36      // A pitch: 32 words + 4 pad
#define PBW 72      // B pitch: 64 words + 8 pad
#define SA_H 0
#define SA_L 4608   // 128*36
#define SB_H 9216
#define SB_L 11520  // +32*72
#define SMEM_WORDS 13824
#define SMEM_BYTES (SMEM_WORDS * 4)   // 55296 -> 2 CTAs/SM

// Epilogue modes
#define EPI_PLAIN 0   // fp32 C[m][n]
#define EPI_A     1   // pack along n (C consumed as A with k = n): direct
#define EPI_B     2   // pack along m (C consumed as B with k = m): smem stage
#define EPI_AT    3   // transposed + pack along m (kT): smem stage

// ---------------------------------------------------------------------------
// C[m,n] = sum_k A(m,k)B(k,n); A,B packed f16x2 hi/lo word arrays.
// A: [m][k/2] words (stride sAw); B: [k/2][n] words (stride sBw).
// Tile 128(M) x 64(N) x 64(K). 256 thr, 8 warps (4m x 2n), warp tile 32x32.
// ---------------------------------------------------------------------------
template <int EPI>
__global__ void __launch_bounds__(256, 2)
gemm7(const uint32_t* __restrict__ Ah, const uint32_t* __restrict__ Al,
      const uint32_t* __restrict__ Bh, const uint32_t* __restrict__ Bl,
      float* __restrict__ Cf, uint32_t* __restrict__ Ch, uint32_t* __restrict__ Cl,
      int K, long long sAw, long long sBw, long long ldC,
      long long bA, long long bB, long long bC)
{
    extern __shared__ uint32_t smw[];
    const uint32_t smb = smem_u32(smw);

    const int tid = threadIdx.x, wid = tid >> 5, lane = tid & 31;
    const int gid = lane >> 2, tig = lane & 3;
    const int wm = (wid & 3) << 5;     // 0,32,64,96
    const int wn = (wid >> 2) << 5;    // 0,32

    const uint32_t* Abh = Ah + (long long)blockIdx.z * bA;
    const uint32_t* Abl = Al + (long long)blockIdx.z * bA;
    const uint32_t* Bbh = Bh + (long long)blockIdx.z * bB;
    const uint32_t* Bbl = Bl + (long long)blockIdx.z * bB;
    const long long bm = (long long)blockIdx.y << 7;
    const long long bn = (long long)blockIdx.x << 6;

    float acc[2][4][4];
#pragma unroll
    for (int mt = 0; mt < 2; mt++)
#pragma unroll
        for (int nt = 0; nt < 4; nt++)
#pragma unroll
            for (int r = 0; r < 4; r++) acc[mt][nt][r] = 0.0f;

    const int nch = K >> 6;            // Kchunk = 64 elems = 32 words
    for (int ic = 0; ic < nch; ic++) {
        const long long k0w = (long long)ic << 5;

        // ---- A tile: 128 rows x 32 words, hi+lo ----
#pragma unroll
        for (int i = 0; i < 4; i++) {
            int idx = tid + (i << 8);                 // 0..1023
            int row = idx >> 3, g4 = (idx & 7) << 2;  // 8 x 16B per row
            uint32_t d = smb + (uint32_t)((row * PAW + g4) << 2);
            cpa16(d,               Abh + (bm + row) * sAw + k0w + g4);
            cpa16(d + (SA_L << 2), Abl + (bm + row) * sAw + k0w + g4);
        }
        // ---- B tile: 32 word-rows x 64 words, hi+lo ----
#pragma unroll
        for (int i = 0; i < 2; i++) {
            int idx = tid + (i << 8);                 // 0..511
            int wr = idx >> 4, g4 = (idx & 15) << 2;  // 16 x 16B per word-row
            uint32_t d = smb + (uint32_t)((SB_H + wr * PBW + g4) << 2);
            cpa16(d,                        Bbh + (k0w + wr) * sBw + bn + g4);
            cpa16(d + ((SB_L - SB_H) << 2), Bbl + (k0w + wr) * sBw + bn + g4);
        }
        asm volatile("cp.async.commit_group;" ::: "memory");
        asm volatile("cp.async.wait_group 0;" ::: "memory");
        __syncthreads();

        // ---- 4 ksteps of k16 (8 words each) ----
#pragma unroll
        for (int ks = 0; ks < 4; ks++) {
            const int kb = ks << 3;
            uint32_t ah[2][4], al[2][4], bh[4][2], bl[4][2];
#pragma unroll
            for (int mt = 0; mt < 2; mt++) {
                int r0 = wm + (mt << 4) + gid;
                int c0 = kb + tig;
                ah[mt][0] = smw[SA_H + r0 * PAW + c0];
                ah[mt][1] = smw[SA_H + (r0 + 8) * PAW + c0];
                ah[mt][2] = smw[SA_H + r0 * PAW + c0 + 4];
                ah[mt][3] = smw[SA_H + (r0 + 8) * PAW + c0 + 4];
                al[mt][0] = smw[SA_L + r0 * PAW + c0];
                al[mt][1] = smw[SA_L + (r0 + 8) * PAW + c0];
                al[mt][2] = smw[SA_L + r0 * PAW + c0 + 4];
                al[mt][3] = smw[SA_L + (r0 + 8) * PAW + c0 + 4];
            }
#pragma unroll
            for (int nt = 0; nt < 4; nt++) {
                int cc = wn + (nt << 3) + gid;
                bh[nt][0] = smw[SB_H + (kb + tig) * PBW + cc];
                bh[nt][1] = smw[SB_H + (kb + tig + 4) * PBW + cc];
                bl[nt][0] = smw[SB_L + (kb + tig) * PBW + cc];
                bl[nt][1] = smw[SB_L + (kb + tig + 4) * PBW + cc];
            }
#pragma unroll
            for (int mt = 0; mt < 2; mt++)
#pragma unroll
                for (int nt = 0; nt < 4; nt++) mma_f16(acc[mt][nt], ah[mt], bh[nt]);
#pragma unroll
            for (int mt = 0; mt < 2; mt++)
#pragma unroll
                for (int nt = 0; nt < 4; nt++) mma_f16(acc[mt][nt], ah[mt], bl[nt]);
#pragma unroll
            for (int mt = 0; mt < 2; mt++)
#pragma unroll
                for (int nt = 0; nt < 4; nt++) mma_f16(acc[mt][nt], al[mt], bh[nt]);
        }
        __syncthreads();
    }

    // ---------------- epilogues ----------------
    if (EPI == EPI_PLAIN) {
        float* Cb = Cf + (long long)blockIdx.z * bC;
#pragma unroll
        for (int mt = 0; mt < 2; mt++) {
            long long r0 = bm + wm + (mt << 4) + gid;
#pragma unroll
            for (int nt = 0; nt < 4; nt++) {
                long long cc = bn + wn + (nt << 3) + (tig << 1);
                *reinterpret_cast<float2*>(Cb + r0 * ldC + cc)       = make_float2(acc[mt][nt][0], acc[mt][nt][1]);
                *reinterpret_cast<float2*>(Cb + (r0 + 8) * ldC + cc) = make_float2(acc[mt][nt][2], acc[mt][nt][3]);
            }
        }
    } else if (EPI == EPI_A) {
        // pack (c0,c1) and (c2,c3) along n: word col = cc/2
        uint32_t* Cbh = Ch + (long long)blockIdx.z * bC;
        uint32_t* Cbl = Cl + (long long)blockIdx.z * bC;
#pragma unroll
        for (int mt = 0; mt < 2; mt++) {
            long long r0 = bm + wm + (mt << 4) + gid;
#pragma unroll
            for (int nt = 0; nt < 4; nt++) {
                long long wc = (bn + wn + (nt << 3) + (tig << 1)) >> 1;
                uint32_t hw, lw;
                splitpack(acc[mt][nt][0], acc[mt][nt][1], hw, lw);
                Cbh[r0 * ldC + wc] = hw; Cbl[r0 * ldC + wc] = lw;
                splitpack(acc[mt][nt][2], acc[mt][nt][3], hw, lw);
                Cbh[(r0 + 8) * ldC + wc] = hw; Cbl[(r0 + 8) * ldC + wc] = lw;
            }
        }
    } else {
        // EPI_B / EPI_AT: stage fp32 tile [128m x 64n] in smem, pitch 65
        float* esm = reinterpret_cast<float*>(smw);
        const int PE = 65;
#pragma unroll
        for (int mt = 0; mt < 2; mt++) {
            int r = wm + (mt << 4) + gid;
#pragma unroll
            for (int nt = 0; nt < 4; nt++) {
                int c = wn + (nt << 3) + (tig << 1);
                esm[r * PE + c]           = acc[mt][nt][0];
                esm[r * PE + c + 1]       = acc[mt][nt][1];
                esm[(r + 8) * PE + c]     = acc[mt][nt][2];
                esm[(r + 8) * PE + c + 1] = acc[mt][nt][3];
            }
        }
        __syncthreads();
        uint32_t* Cbh = Ch + (long long)blockIdx.z * bC;
        uint32_t* Cbl = Cl + (long long)blockIdx.z * bC;
        if (EPI == EPI_B) {
            // word(wr, n) packs rows (2wr, 2wr+1) at col n; global row = bm/2 + wr
            const int n = tid & 63, grp = tid >> 6;   // 4 groups x 16 word-rows
#pragma unroll
            for (int j = 0; j < 16; j++) {
                int wr = grp * 16 + j;
                uint32_t hw, lw;
                splitpack(esm[(2 * wr) * PE + n], esm[(2 * wr + 1) * PE + n], hw, lw);
                long long o = ((bm >> 1) + wr) * ldC + bn + n;
                Cbh[o] = hw; Cbl[o] = lw;
            }
        } else {
            // EPI_AT: kT[i][h]: word(i, wc) packs (C[2wc][i], C[2wc+1][i]); i = n dim
            const int i = tid >> 2, j0 = (tid & 3) << 4;   // 64 rows x 4x16 words
#pragma unroll
            for (int j = 0; j < 16; j++) {
                int wc = j0 + j;
                uint32_t hw, lw;
                splitpack(esm[(2 * wc) * PE + i], esm[(2 * wc + 1) * PE + i], hw, lw);
                long long o = (bn + i) * ldC + (bm >> 1) + wc;
                Cbh[o] = hw; Cbl[o] = lw;
            }
        }
    }
}

// ---------------- input splitters ----------------
// A-format: M[r][c], pack along c. One thread per word.
__global__ void __launch_bounds__(256)
split_wA(const float* __restrict__ src, uint32_t* __restrict__ h, uint32_t* __restrict__ l,
         long long nwords)
{
    long long i = blockIdx.x * 256ll + threadIdx.x;
    if (i >= nwords) return;
    float2 v = reinterpret_cast<const float2*>(src)[i];
    uint32_t hw, lw;
    splitpack(v.x, v.y, hw, lw);
    h[i] = hw; l[i] = lw;
}
// B-format: M[r][c] with rows paired: word(wr, c) = (M[2wr][c], M[2wr+1][c]).
__global__ void __launch_bounds__(256)
split_xB(const float* __restrict__ src, uint32_t* __restrict__ h, uint32_t* __restrict__ l,
         int ncols, long long nwords)
{
    long long i = blockIdx.x * 256ll + threadIdx.x;
    if (i >= nwords) return;
    long long wr = i / ncols, c = i - wr * ncols;
    float x0 = src[(2 * wr) * ncols + c];
    float x1 = src[(2 * wr + 1) * ncols + c];
    uint32_t hw, lw;
    splitpack(x0, x1, hw, lw);
    h[i] = hw; l[i] = lw;
}

// ---------------- softmax on row pairs, packed B-format output ----------------
__global__ void __launch_bounds__(256)
softmax2(const float* __restrict__ S, uint32_t* __restrict__ Sh, uint32_t* __restrict__ Sl, int N)
{
    const float* r0 = S + (long long)(2 * blockIdx.x) * N;
    const float* r1 = r0 + N;
    uint32_t* oh = Sh + (long long)blockIdx.x * N;
    uint32_t* ol = Sl + (long long)blockIdx.x * N;
    const int tid = threadIdx.x;
    __shared__ float red0[256], red1[256];

    float v0[8], v1[8];
    float m0 = -3.4e38f, m1 = -3.4e38f;
#pragma unroll
    for (int i = 0; i < 8; i++) {
        int j = tid + (i << 8);
        v0[i] = r0[j]; v1[i] = r1[j];
        m0 = fmaxf(m0, v0[i]); m1 = fmaxf(m1, v1[i]);
    }
    red0[tid] = m0; red1[tid] = m1;
    __syncthreads();
    for (int s = 128; s > 0; s >>= 1) {
        if (tid < s) {
            red0[tid] = fmaxf(red0[tid], red0[tid + s]);
            red1[tid] = fmaxf(red1[tid], red1[tid + s]);
        }
        __syncthreads();
    }
    m0 = red0[0]; m1 = red1[0];
    __syncthreads();

    float s0 = 0.0f, s1 = 0.0f;
#pragma unroll
    for (int i = 0; i < 8; i++) {
        v0[i] = __expf(v0[i] - m0); s0 += v0[i];
        v1[i] = __expf(v1[i] - m1); s1 += v1[i];
    }
    red0[tid] = s0; red1[tid] = s1;
    __syncthreads();
    for (int s = 128; s > 0; s >>= 1) {
        if (tid < s) { red0[tid] += red0[tid + s]; red1[tid] += red1[tid + s]; }
        __syncthreads();
    }
    float i0 = 1.0f / red0[0], i1 = 1.0f / red1[0];
#pragma unroll
    for (int i = 0; i < 8; i++) {
        int j = tid + (i << 8);
        uint32_t hw, lw;
        splitpack(v0[i] * i0, v1[i] * i1, hw, lw);
        oh[j] = hw; ol[j] = lw;
    }
}

extern "C" void kernel_launch(void* const* d_in, const int* in_sizes, int n_in,
                              void* d_out, int out_size)
{
    const float* x   = (const float*)d_in[0];
    const float* W_Q = (const float*)d_in[1];
    const float* W_K = (const float*)d_in[2];
    const float* W_V = (const float*)d_in[3];
    const float* W_O = (const float*)d_in[4];
    float*       out = (float*)d_out;

    uint32_t *xBh,*xBl,*wqh,*wql,*wkh,*wkl,*wvh,*wvl,*woh,*wol;
    uint32_t *qBh,*qBl,*ktAh,*ktAl,*vAh,*vAl,*sBh,*sBl,*aBh,*aBl;
    float *s;
    cudaGetSymbolAddress((void**)&xBh, g_xBh); cudaGetSymbolAddress((void**)&xBl, g_xBl);
    cudaGetSymbolAddress((void**)&wqh, g_wqh); cudaGetSymbolAddress((void**)&wql, g_wql);
    cudaGetSymbolAddress((void**)&wkh, g_wkh); cudaGetSymbolAddress((void**)&wkl, g_wkl);
    cudaGetSymbolAddress((void**)&wvh, g_wvh); cudaGetSymbolAddress((void**)&wvl, g_wvl);
    cudaGetSymbolAddress((void**)&woh, g_woh); cudaGetSymbolAddress((void**)&wol, g_wol);
    cudaGetSymbolAddress((void**)&qBh, g_qBh); cudaGetSymbolAddress((void**)&qBl, g_qBl);
    cudaGetSymbolAddress((void**)&ktAh, g_ktAh); cudaGetSymbolAddress((void**)&ktAl, g_ktAl);
    cudaGetSymbolAddress((void**)&vAh, g_vAh); cudaGetSymbolAddress((void**)&vAl, g_vAl);
    cudaGetSymbolAddress((void**)&s,   g_s);
    cudaGetSymbolAddress((void**)&sBh, g_sBh); cudaGetSymbolAddress((void**)&sBl, g_sBl);
    cudaGetSymbolAddress((void**)&aBh, g_aBh); cudaGetSymbolAddress((void**)&aBl, g_aBl);

    cudaFuncSetAttribute(gemm7<EPI_PLAIN>, cudaFuncAttributeMaxDynamicSharedMemorySize, SMEM_BYTES);
    cudaFuncSetAttribute(gemm7<EPI_A>,     cudaFuncAttributeMaxDynamicSharedMemorySize, SMEM_BYTES);
    cudaFuncSetAttribute(gemm7<EPI_B>,     cudaFuncAttributeMaxDynamicSharedMemorySize, SMEM_BYTES);
    cudaFuncSetAttribute(gemm7<EPI_AT>,    cudaFuncAttributeMaxDynamicSharedMemorySize, SMEM_BYTES);

    // word-space batch strides
    const long long xBb = (long long)(DDIM/2) * NSEQ;   // 1M words
    const long long qBb = (long long)(MH/2) * NSEQ;
    const long long ktb = (long long)NSEQ * (MH/2);
    const long long vAb = (long long)MV * (NSEQ/2);
    const long long sBb = (long long)(NSEQ/2) * NSEQ;
    const long long aBb = (long long)(MV/2) * NSEQ;
    const long long sFb = (long long)NSEQ * NSEQ;       // fp32
    const long long oFb = (long long)DDIM * NSEQ;       // fp32

    // ---- split inputs ----
    split_wA<<<(MH * DDIM / 2 + 255) / 256, 256>>>(W_Q, wqh, wql, (long long)MH * DDIM / 2);
    split_wA<<<(MH * DDIM / 2 + 255) / 256, 256>>>(W_K, wkh, wkl, (long long)MH * DDIM / 2);
    split_wA<<<(MV * DDIM / 2 + 255) / 256, 256>>>(W_V, wvh, wvl, (long long)MV * DDIM / 2);
    split_wA<<<(DDIM * MV / 2 + 255) / 256, 256>>>(W_O, woh, wol, (long long)DDIM * MV / 2);
    for (int b = 0; b < BATCH; b++)
        split_xB<<<((DDIM/2) * NSEQ + 255) / 256, 256>>>(
            x + (long long)b * DDIM * NSEQ, xBh + b * xBb, xBl + b * xBb,
            NSEQ, (long long)(DDIM/2) * NSEQ);

    // ---- projections ----
    {
        dim3 g(NSEQ / 64, MH / 128, BATCH);
        // q -> B-format (pack along m=h); ldC = NSEQ words
        gemm7<EPI_B><<<g, 256, SMEM_BYTES>>>(wqh, wql, xBh, xBl, nullptr, qBh, qBl,
                                             DDIM, DDIM/2, NSEQ, NSEQ, 0, xBb, qBb);
        // kT -> A-format transposed (pack along m=h); ldC = MH/2 words
        gemm7<EPI_AT><<<g, 256, SMEM_BYTES>>>(wkh, wkl, xBh, xBl, nullptr, ktAh, ktAl,
                                              DDIM, DDIM/2, NSEQ, MH/2, 0, xBb, ktb);
        // v -> A-format (pack along n=i); ldC = NSEQ/2 words
        gemm7<EPI_A><<<g, 256, SMEM_BYTES>>>(wvh, wvl, xBh, xBl, nullptr, vAh, vAl,
                                             DDIM, DDIM/2, NSEQ, NSEQ/2, 0, xBb, vAb);
    }
    // ---- scores (plain fp32) ----
    {
        dim3 g(NSEQ / 64, NSEQ / 128, BATCH);
        gemm7<EPI_PLAIN><<<g, 256, SMEM_BYTES>>>(ktAh, ktAl, qBh, qBl, s, nullptr, nullptr,
                                                 MH, MH/2, NSEQ, NSEQ, ktb, qBb, sFb);
    }
    // ---- softmax row-pairs -> packed B-format ----
    softmax2<<<BATCH * NSEQ / 2, 256>>>(s, sBh, sBl, NSEQ);
    // ---- attn = V @ S -> B-format (pack along m=v) ----
    {
        dim3 g(NSEQ / 64, MV / 128, BATCH);
        gemm7<EPI_B><<<g, 256, SMEM_BYTES>>>(vAh, vAl, sBh, sBl, nullptr, aBh, aBl,
                                             NSEQ, NSEQ/2, NSEQ, NSEQ, vAb, sBb, aBb);
    }
    // ---- out = W_O @ attn (plain fp32) ----
    {
        dim3 g(NSEQ / 64, DDIM / 128, BATCH);
        gemm7<EPI_PLAIN><<<g, 256, SMEM_BYTES>>>(woh, wol, aBh, aBl, out, nullptr, nullptr,
                                                 MV, MV/2, NSEQ, NSEQ, 0, aBb, oFb);
    }
}